// round 10
// baseline (speedup 1.0000x reference)
#include <cuda_runtime.h>
#include <cstdint>

// RoiDeform: output (B=2, k*k=16, cs=384, cs=384, C=3) fp32.
// All 384 output rows within a bin are identical.
// Single fused kernel, 1024 blocks x 288 threads:
//   rowid = bid % 32 (leaders = bids 0..31, scheduled first -> no deadlock)
//   chunk = bid / 32 (each block writes 12 of the 384 identical rows)
// Leaders compute their bin's sampled row once into g_row, release a flag,
// then join the common broadcast path. Followers spin briefly on the flag.
// Broadcast uses 256-bit STG (st.global.v8.b32, sm_100+/sm_103a) to halve
// the L2 store-request count: threads 0..143 write row r, 144..287 row r+1.

#define BATCH 2
#define IMG_H 1600
#define IMG_W 1600
#define CH 3
#define KK 4
#define CS 384
#define PAD 32                     // (1600 - 384*4)/2
#define ROW_FLOATS (CS * CH)       // 1152
#define ROW_F8 (ROW_FLOATS / 8)    // 144 x 32B chunks per row
#define NROWS (BATCH * KK * KK)    // 32 unique rows
#define RPB 12                     // rows written per block
#define CHUNKS (CS / RPB)          // 32
#define THREADS 288                // 9 warps; 2 row-halves of 144 threads

__device__ __align__(32) float g_row[NROWS * ROW_FLOATS];  // 147 KB scratch
__device__ int g_flag[NROWS];                              // zero-initialized

__device__ __forceinline__ void sample_one(const float* __restrict__ img,
                                           int b, int bi, int bj, int s,
                                           float dp0, float dp1,
                                           float* __restrict__ dst)
{
    const float r = (float)(PAD + bi * CS + s) + dp0;
    const float c = (float)(PAD + bj * CS + s) + dp1;
    const float r0f = floorf(r);
    const float c0f = floorf(c);
    const float rf = r - r0f;
    const float cf = c - c0f;
    const int r0 = (int)r0f;
    const int c0 = (int)c0f;

    float a0 = 0.f, a1 = 0.f, a2 = 0.f;
    #pragma unroll
    for (int dr = 0; dr < 2; ++dr) {
        const int   ri = r0 + dr;
        const float wr = dr ? rf : (1.0f - rf);
        if (ri >= 0 && ri < IMG_H) {
            #pragma unroll
            for (int dc = 0; dc < 2; ++dc) {
                const int   ci = c0 + dc;
                const float wc = dc ? cf : (1.0f - cf);
                if (ci >= 0 && ci < IMG_W) {
                    const float w = wr * wc;
                    const float* p = img +
                        ((size_t)((size_t)b * IMG_H + ri) * IMG_W + ci) * CH;
                    a0 += w * __ldg(p + 0);
                    a1 += w * __ldg(p + 1);
                    a2 += w * __ldg(p + 2);
                }
            }
        }
    }
    dst[0] = a0;
    dst[1] = a1;
    dst[2] = a2;
}

__global__ __launch_bounds__(THREADS)
void roi_deform_fused(const float* __restrict__ img,
                      const float* __restrict__ delta_p,
                      float* __restrict__ out)
{
    const int bid   = blockIdx.x;          // 0..1023
    const int rowid = bid & (NROWS - 1);   // bid % 32
    const int chunk = bid >> 5;            // bid / 32, 0..31
    const int t     = threadIdx.x;         // 0..287

    if (chunk == 0) {
        // ---- Leader: compute this bin's sampled row once ----
        const int b   = rowid >> 4;
        const int bin = rowid & 15;
        const int bi  = bin >> 2;
        const int bj  = bin & 3;
        const float dp0 = __ldg(&delta_p[rowid * 2 + 0]);
        const float dp1 = __ldg(&delta_p[rowid * 2 + 1]);
        float* rowp = g_row + (size_t)rowid * ROW_FLOATS;

        sample_one(img, b, bi, bj, t, dp0, dp1, rowp + t * 3);
        if (t < CS - THREADS) {  // t < 96: second sample s = 288 + t
            sample_one(img, b, bi, bj, THREADS + t, dp0, dp1,
                       rowp + (THREADS + t) * 3);
        }
        __syncthreads();
        __threadfence();
        if (t == 0) {
            *(volatile int*)&g_flag[rowid] = 1;
        }
        __syncthreads();
    } else {
        // ---- Follower: wait for our row to be published ----
        if (t == 0) {
            while (*(volatile int*)&g_flag[rowid] == 0) {
                __nanosleep(16);
            }
            __threadfence();   // acquire: order subsequent g_row reads
        }
        __syncthreads();
    }

    // ---- Common broadcast: 12 identical rows via 256-bit stores ----
    // half = 0 -> even rows, half = 1 -> odd rows; q = 32B-chunk index in row.
    const int half = t / ROW_F8;           // 0 or 1
    const int q    = t - half * ROW_F8;    // 0..143

    uint32_t v0, v1, v2, v3, v4, v5, v6, v7;
    {
        const float* srcp = g_row + (size_t)rowid * ROW_FLOATS + q * 8;
        asm volatile(
            "ld.global.nc.v8.b32 {%0,%1,%2,%3,%4,%5,%6,%7}, [%8];"
            : "=r"(v0), "=r"(v1), "=r"(v2), "=r"(v3),
              "=r"(v4), "=r"(v5), "=r"(v6), "=r"(v7)
            : "l"(srcp));
    }

    // First destination row for this thread: chunk*RPB + half, step 2 rows.
    char* dst = (char*)out +
                (((size_t)rowid * CS + (size_t)chunk * RPB + half) * ROW_F8 + q)
                    * 32;
    const size_t step = (size_t)2 * ROW_F8 * 32;   // 2 rows = 9216 B

    #pragma unroll
    for (int it = 0; it < RPB / 2; ++it) {
        asm volatile(
            "st.global.v8.b32 [%0], {%1,%2,%3,%4,%5,%6,%7,%8};"
            :: "l"(dst), "r"(v0), "r"(v1), "r"(v2), "r"(v3),
               "r"(v4), "r"(v5), "r"(v6), "r"(v7)
            : "memory");
        dst += step;
    }
}

extern "C" void kernel_launch(void* const* d_in, const int* in_sizes, int n_in,
                              void* d_out, int out_size)
{
    const float* img = (const float*)d_in[0];
    const float* dp  = (const float*)d_in[1];
    float* out = (float*)d_out;
    (void)in_sizes; (void)n_in; (void)out_size;

    roi_deform_fused<<<CHUNKS * NROWS, THREADS>>>(img, dp, out);  // 1024 blocks
}

// round 11
// speedup vs baseline: 1.1272x; 1.1272x over previous
#include <cuda_runtime.h>
#include <cstdint>

// RoiDeform: output (B=2, k*k=16, cs=384, cs=384, C=3) fp32.
// All 384 output rows within a bin are identical.
// Single fused kernel, 1024 blocks x 288 threads:
//   rowid = bid % 32 (leaders = bids 0..31, scheduled first -> no deadlock)
//   chunk = bid / 32 (each block writes 12 of the 384 identical rows)
// Leaders compute their bin's sampled row once into g_row and publish it with
// a release-store flag; followers spin on a per-thread acquire-load, then all
// blocks stream 12 identical rows with coalesced STG.128 (the ~5 TB/s
// L2-write-path floor; STG.256 measured slower in R10).

#define BATCH 2
#define IMG_H 1600
#define IMG_W 1600
#define CH 3
#define KK 4
#define CS 384
#define PAD 32                     // (1600 - 384*4)/2
#define ROW_FLOATS (CS * CH)       // 1152
#define ROW_F4 (ROW_FLOATS / 4)    // 288
#define NROWS (BATCH * KK * KK)    // 32 unique rows
#define RPB 12                     // rows written per block
#define CHUNKS (CS / RPB)          // 32
#define THREADS 288                // 9 warps = ROW_F4 threads

__device__ __align__(16) float g_row[NROWS * ROW_FLOATS];  // 147 KB scratch
__device__ int g_flag[NROWS];                              // zero-initialized

__device__ __forceinline__ void sample_one(const float* __restrict__ img,
                                           int b, int bi, int bj, int s,
                                           float dp0, float dp1,
                                           float* __restrict__ dst)
{
    const float r = (float)(PAD + bi * CS + s) + dp0;
    const float c = (float)(PAD + bj * CS + s) + dp1;
    const float r0f = floorf(r);
    const float c0f = floorf(c);
    const float rf = r - r0f;
    const float cf = c - c0f;
    const int r0 = (int)r0f;
    const int c0 = (int)c0f;

    float a0 = 0.f, a1 = 0.f, a2 = 0.f;
    #pragma unroll
    for (int dr = 0; dr < 2; ++dr) {
        const int   ri = r0 + dr;
        const float wr = dr ? rf : (1.0f - rf);
        if (ri >= 0 && ri < IMG_H) {
            #pragma unroll
            for (int dc = 0; dc < 2; ++dc) {
                const int   ci = c0 + dc;
                const float wc = dc ? cf : (1.0f - cf);
                if (ci >= 0 && ci < IMG_W) {
                    const float w = wr * wc;
                    const float* p = img +
                        ((size_t)((size_t)b * IMG_H + ri) * IMG_W + ci) * CH;
                    a0 += w * __ldg(p + 0);
                    a1 += w * __ldg(p + 1);
                    a2 += w * __ldg(p + 2);
                }
            }
        }
    }
    dst[0] = a0;
    dst[1] = a1;
    dst[2] = a2;
}

__global__ __launch_bounds__(THREADS)
void roi_deform_fused(const float* __restrict__ img,
                      const float* __restrict__ delta_p,
                      float* __restrict__ out)
{
    const int bid   = blockIdx.x;          // 0..1023
    const int rowid = bid & (NROWS - 1);   // bid % 32
    const int chunk = bid >> 5;            // bid / 32, 0..31
    const int t     = threadIdx.x;         // 0..287

    if (chunk == 0) {
        // ---- Leader: compute this bin's sampled row once ----
        const int b   = rowid >> 4;
        const int bin = rowid & 15;
        const int bi  = bin >> 2;
        const int bj  = bin & 3;
        const float dp0 = __ldg(&delta_p[rowid * 2 + 0]);
        const float dp1 = __ldg(&delta_p[rowid * 2 + 1]);
        float* rowp = g_row + (size_t)rowid * ROW_FLOATS;

        sample_one(img, b, bi, bj, t, dp0, dp1, rowp + t * 3);
        if (t < CS - THREADS) {  // t < 96: second (independent) sample
            sample_one(img, b, bi, bj, THREADS + t, dp0, dp1,
                       rowp + (THREADS + t) * 3);
        }
        __syncthreads();               // all row writes of this block done
        if (t == 0) {
            asm volatile("st.global.release.gpu.b32 [%0], %1;"
                         :: "l"(&g_flag[rowid]), "r"(1) : "memory");
        }
    } else {
        // ---- Follower: every thread spins on its own acquire-load ----
        int f;
        do {
            asm volatile("ld.global.acquire.gpu.b32 %0, [%1];"
                         : "=r"(f) : "l"(&g_flag[rowid]) : "memory");
            if (f) break;
            __nanosleep(16);
        } while (true);
    }

    // ---- Common broadcast: write RPB identical rows, STG.128 coalesced ----
    const float4 v = __ldg(reinterpret_cast<const float4*>(
                               g_row + (size_t)rowid * ROW_FLOATS) + t);
    float4* out4 = reinterpret_cast<float4*>(out) +
                   ((size_t)rowid * CS + (size_t)chunk * RPB) * ROW_F4 + t;
    #pragma unroll
    for (int r = 0; r < RPB; ++r) {
        out4[(size_t)r * ROW_F4] = v;
    }
}

extern "C" void kernel_launch(void* const* d_in, const int* in_sizes, int n_in,
                              void* d_out, int out_size)
{
    const float* img = (const float*)d_in[0];
    const float* dp  = (const float*)d_in[1];
    float* out = (float*)d_out;
    (void)in_sizes; (void)n_in; (void)out_size;

    roi_deform_fused<<<CHUNKS * NROWS, THREADS>>>(img, dp, out);  // 1024 blocks
}